// round 5
// baseline (speedup 1.0000x reference)
#include <cuda_runtime.h>
#include <cstdint>

// out[b][o][i][l] = white_table[o][i][ x[b][i][o][l] ]
// B=8, O=I=64, L=2048. L contiguous on both sides -> fully coalesced vec4.
// Single-wave persistent grid: 1184 blocks (8/SM x 148 SMs), grid-stride over
// the 4096 (o,i) pairs. Per pair: 1KB LUT to smem, stream 8 batches vec4.

#define B_DIM 8
#define CH 64
#define L_DIM 2048
#define THREADS 256
#define GRID 1184            // 148 SMs * 8 blocks/SM -> exactly one wave
#define NPAIRS (CH * CH)     // 4096

__global__ __launch_bounds__(THREADS) void white_transpose_kernel(
    const int* __restrict__ x,
    const float* __restrict__ table,
    float* __restrict__ out)
{
    __shared__ float lut[256];

    const size_t bstride4 = (size_t)CH * CH * (L_DIM / 4);  // int4 units per batch

    for (int idx = blockIdx.x; idx < NPAIRS; idx += GRID) {
        const int i = idx & (CH - 1);
        const int o = idx >> 6;

        __syncthreads();   // protect lut against previous iteration's readers
        if (threadIdx.x < 256)
            lut[threadIdx.x] = table[((o * CH + i) << 8) + threadIdx.x];
        __syncthreads();

        const int4* __restrict__ xin =
            reinterpret_cast<const int4*>(x) + (size_t)(i * CH + o) * (L_DIM / 4);
        float4* __restrict__ op =
            reinterpret_cast<float4*>(out) + (size_t)(o * CH + i) * (L_DIM / 4);

        #pragma unroll
        for (int b = 0; b < B_DIM; b++) {
            const size_t base = b * bstride4;
            #pragma unroll
            for (int v = 0; v < (L_DIM / 4) / THREADS; v++) {
                const int vi = v * THREADS + threadIdx.x;
                int4 xi = xin[base + vi];
                float4 r;
                r.x = lut[xi.x];
                r.y = lut[xi.y];
                r.z = lut[xi.z];
                r.w = lut[xi.w];
                op[base + vi] = r;
            }
        }
    }
}

extern "C" void kernel_launch(void* const* d_in, const int* in_sizes, int n_in,
                              void* d_out, int out_size)
{
    const int* x = (const int*)d_in[0];          // [8, 64, 64, 2048] int32
    const float* table = (const float*)d_in[1];  // [64, 64, 256] float32
    float* out = (float*)d_out;                  // [8, 64, 64, 2048] float32

    white_transpose_kernel<<<GRID, THREADS>>>(x, table, out);
}

// round 7
// speedup vs baseline: 1.1135x; 1.1135x over previous
#include <cuda_runtime.h>
#include <cstdint>

// out[b][o][i][l] = white_table[o][i][ x[b][i][o][l] ]
// B=8, O=I=64, L=2048. L contiguous on both sides -> fully coalesced vec4.
// One block per (o,i) pair (grid 4096, best-measured shape). Single change vs
// R2: batch-0 x loads are issued BEFORE the LUT smem fill + barrier, so the
// ~600cyc table LDG latency overlaps with stream traffic instead of stalling
// the whole block at startup.

#define B_DIM 8
#define CH 64
#define L_DIM 2048
#define THREADS 256

__global__ __launch_bounds__(THREADS) void white_transpose_kernel(
    const int* __restrict__ x,
    const float* __restrict__ table,
    float* __restrict__ out)
{
    const int idx = blockIdx.x;          // 0..4095
    const int i = idx & (CH - 1);
    const int o = idx >> 6;

    const size_t bstride4 = (size_t)CH * CH * (L_DIM / 4);  // int4 units per batch
    const int4* __restrict__ xin =
        reinterpret_cast<const int4*>(x) + (size_t)(i * CH + o) * (L_DIM / 4);
    float4* __restrict__ op =
        reinterpret_cast<float4*>(out) + (size_t)(o * CH + i) * (L_DIM / 4);

    // Prefetch batch 0 (independent of the table) before the LUT barrier.
    const int vi0 = threadIdx.x;
    const int vi1 = THREADS + threadIdx.x;
    int4 p0 = xin[vi0];
    int4 p1 = xin[vi1];

    __shared__ float lut[256];
    lut[threadIdx.x] = table[((o * CH + i) << 8) + threadIdx.x];
    __syncthreads();

    // Batch 0 from prefetched registers.
    {
        float4 r0, r1;
        r0.x = lut[p0.x]; r0.y = lut[p0.y]; r0.z = lut[p0.z]; r0.w = lut[p0.w];
        r1.x = lut[p1.x]; r1.y = lut[p1.y]; r1.z = lut[p1.z]; r1.w = lut[p1.w];
        op[vi0] = r0;
        op[vi1] = r1;
    }

    // Batches 1..7: identical to the best-measured R2 stream.
    #pragma unroll
    for (int b = 1; b < B_DIM; b++) {
        const size_t base = b * bstride4;
        #pragma unroll
        for (int v = 0; v < (L_DIM / 4) / THREADS; v++) {
            const int vi = v * THREADS + threadIdx.x;
            int4 xi = xin[base + vi];
            float4 r;
            r.x = lut[xi.x];
            r.y = lut[xi.y];
            r.z = lut[xi.z];
            r.w = lut[xi.w];
            op[base + vi] = r;
        }
    }
}

extern "C" void kernel_launch(void* const* d_in, const int* in_sizes, int n_in,
                              void* d_out, int out_size)
{
    const int* x = (const int*)d_in[0];          // [8, 64, 64, 2048] int32
    const float* table = (const float*)d_in[1];  // [64, 64, 256] float32
    float* out = (float*)d_out;                  // [8, 64, 64, 2048] float32

    const int grid = CH * CH;  // 4096 blocks, one per (o,i)
    white_transpose_kernel<<<grid, THREADS>>>(x, table, out);
}